// round 2
// baseline (speedup 1.0000x reference)
#include <cuda_runtime.h>
#include <cstdint>

#define B_   64
#define T_   4096
#define NIN  64
#define U_   128
#define NOUT 64
#define CCH  64
#define LCH  64

// ---------------------------------------------------------------------------
// Static device scratch
// ---------------------------------------------------------------------------
__device__ float g_Ky[B_ * T_ * U_];        // 128 MB
__device__ float g_E[B_ * CCH * U_];
__device__ float g_carry[B_ * CCH * U_];
__device__ float g_P2[U_ * U_], g_P4[U_ * U_], g_P8[U_ * U_];
__device__ float g_P16[U_ * U_], g_P32[U_ * U_], g_P64[U_ * U_];
__device__ float g_Wt[U_ * LCH * NOUT];     // [k][step][o]  (2 MB)

// ---------------------------------------------------------------------------
// Packed f32x2 helpers
// ---------------------------------------------------------------------------
__device__ __forceinline__ unsigned long long ffma2(unsigned long long a,
                                                    unsigned long long b,
                                                    unsigned long long c) {
    unsigned long long d;
    asm("fma.rn.f32x2 %0, %1, %2, %3;" : "=l"(d) : "l"(a), "l"(b), "l"(c));
    return d;
}
__device__ __forceinline__ unsigned long long dup2(float v) {
    unsigned long long r;
    asm("mov.b64 %0, {%1, %1};" : "=l"(r) : "f"(v));
    return r;
}
__device__ __forceinline__ unsigned long long pack2(float x, float y) {
    unsigned long long r;
    asm("mov.b64 %0, {%1, %2};" : "=l"(r) : "f"(x), "f"(y));
    return r;
}
__device__ __forceinline__ float2 unpack2(unsigned long long v) {
    float2 f;
    asm("mov.b64 {%0, %1}, %2;" : "=f"(f.x), "=f"(f.y) : "l"(v));
    return f;
}

// ---------------------------------------------------------------------------
// K1: Ky = x @ KT   ([B*T,64] @ [64,128])
// ---------------------------------------------------------------------------
__global__ __launch_bounds__(128) void ky_kernel(const float* __restrict__ x,
                                                 const float* __restrict__ KT) {
    const int u = threadIdx.x;
    float kt[NIN];
#pragma unroll
    for (int n = 0; n < NIN; n++) kt[n] = KT[n * U_ + u];

    __shared__ __align__(16) float xs[NIN * 8];
    const int row0 = blockIdx.x * 256;

#pragma unroll 1
    for (int tile = 0; tile < 32; tile++) {
        const int r0 = row0 + tile * 8;
        float4 xv = reinterpret_cast<const float4*>(x + (size_t)r0 * NIN)[u];
        __syncthreads();
        {
            const int rr = u >> 4;
            const int n0 = (u & 15) * 4;
            xs[(n0 + 0) * 8 + rr] = xv.x;
            xs[(n0 + 1) * 8 + rr] = xv.y;
            xs[(n0 + 2) * 8 + rr] = xv.z;
            xs[(n0 + 3) * 8 + rr] = xv.w;
        }
        __syncthreads();

        unsigned long long acc[4] = {0ull, 0ull, 0ull, 0ull};
#pragma unroll
        for (int n = 0; n < NIN; n++) {
            unsigned long long kv = dup2(kt[n]);
            ulonglong2 a = *reinterpret_cast<const ulonglong2*>(&xs[n * 8]);
            ulonglong2 b = *reinterpret_cast<const ulonglong2*>(&xs[n * 8 + 4]);
            acc[0] = ffma2(a.x, kv, acc[0]);
            acc[1] = ffma2(a.y, kv, acc[1]);
            acc[2] = ffma2(b.x, kv, acc[2]);
            acc[3] = ffma2(b.y, kv, acc[3]);
        }
#pragma unroll
        for (int i = 0; i < 4; i++) {
            float2 f = unpack2(acc[i]);
            g_Ky[(size_t)(r0 + 2 * i)     * U_ + u] = f.x;
            g_Ky[(size_t)(r0 + 2 * i + 1) * U_ + u] = f.y;
        }
    }
}

// ---------------------------------------------------------------------------
// K2: O = A @ A  (128x128) — 4 partial accumulators, full-unroll MLP
// ---------------------------------------------------------------------------
__global__ __launch_bounds__(128) void matsq(const float* __restrict__ A,
                                             float* __restrict__ O) {
    const int r = blockIdx.x, u = threadIdx.x;
    __shared__ float row[U_];
    row[u] = A[r * U_ + u];
    __syncthreads();
    float a0 = 0.f, a1 = 0.f, a2 = 0.f, a3 = 0.f;
#pragma unroll
    for (int k = 0; k < U_; k += 4) {
        a0 = fmaf(row[k + 0], A[(k + 0) * U_ + u], a0);
        a1 = fmaf(row[k + 1], A[(k + 1) * U_ + u], a1);
        a2 = fmaf(row[k + 2], A[(k + 2) * U_ + u], a2);
        a3 = fmaf(row[k + 3], A[(k + 3) * U_ + u], a3);
    }
    O[r * U_ + u] = (a0 + a1) + (a2 + a3);
}

// ---------------------------------------------------------------------------
// K3: single recurrence pass, zero-init, fused y1 = S_local @ CyT, emits E.
// 16 batches/CTA, grid (64 chunks, 4 batch groups) = 256 CTAs = one wave.
// ---------------------------------------------------------------------------
__global__ __launch_bounds__(128, 2) void scan1(const float* __restrict__ AT,
                                                const float* __restrict__ CyT,
                                                float* __restrict__ y) {
    const int c = blockIdx.x, bg = blockIdx.y, u = threadIdx.x;
    const int b0 = bg * 16;

    __shared__ __align__(16) float s_sh[2][U_ * 16];   // 16 KB
    __shared__ __align__(16) float cy_sh[U_ * NOUT];   // 32 KB  (total 48 KB)

    float at[U_];
#pragma unroll
    for (int k = 0; k < U_; k++) at[k] = AT[k * U_ + u];

#pragma unroll 1
    for (int i = u; i < U_ * NOUT; i += 128) cy_sh[i] = CyT[i];
#pragma unroll
    for (int j = 0; j < 16; j++) s_sh[0][u * 16 + j] = 0.f;
    __syncthreads();

    float kyc[16];
#pragma unroll
    for (int j = 0; j < 16; j++)
        kyc[j] = g_Ky[((size_t)(b0 + j) * T_ + c * LCH) * U_ + u];

    const int o = u & 63, bs = u >> 6;
    int p = 0;

#pragma unroll 1
    for (int step = 0; step < LCH; step++) {
        const int t = c * LCH + step;

        float kyn[16];
        if (step < LCH - 1) {
#pragma unroll
            for (int j = 0; j < 16; j++)
                kyn[j] = g_Ky[((size_t)(b0 + j) * T_ + t + 1) * U_ + u];
        } else {
#pragma unroll
            for (int j = 0; j < 16; j++) kyn[j] = 0.f;
        }

        unsigned long long acc[8];
#pragma unroll
        for (int i = 0; i < 8; i++) acc[i] = pack2(kyc[2 * i], kyc[2 * i + 1]);

#pragma unroll
        for (int k = 0; k < U_; k++) {
            const unsigned long long av = dup2(at[k]);
            const ulonglong2 s0 = *(const ulonglong2*)&s_sh[p][k * 16 + 0];
            const ulonglong2 s1 = *(const ulonglong2*)&s_sh[p][k * 16 + 4];
            const ulonglong2 s2 = *(const ulonglong2*)&s_sh[p][k * 16 + 8];
            const ulonglong2 s3 = *(const ulonglong2*)&s_sh[p][k * 16 + 12];
            acc[0] = ffma2(s0.x, av, acc[0]);
            acc[1] = ffma2(s0.y, av, acc[1]);
            acc[2] = ffma2(s1.x, av, acc[2]);
            acc[3] = ffma2(s1.y, av, acc[3]);
            acc[4] = ffma2(s2.x, av, acc[4]);
            acc[5] = ffma2(s2.y, av, acc[5]);
            acc[6] = ffma2(s3.x, av, acc[6]);
            acc[7] = ffma2(s3.y, av, acc[7]);
        }

        const int q = p ^ 1;
        {
            float2 f0 = unpack2(acc[0]), f1 = unpack2(acc[1]);
            float2 f2 = unpack2(acc[2]), f3 = unpack2(acc[3]);
            float2 f4 = unpack2(acc[4]), f5 = unpack2(acc[5]);
            float2 f6 = unpack2(acc[6]), f7 = unpack2(acc[7]);
            float4* dst = (float4*)&s_sh[q][u * 16];
            dst[0] = make_float4(f0.x, f0.y, f1.x, f1.y);
            dst[1] = make_float4(f2.x, f2.y, f3.x, f3.y);
            dst[2] = make_float4(f4.x, f4.y, f5.x, f5.y);
            dst[3] = make_float4(f6.x, f6.y, f7.x, f7.y);
        }
        __syncthreads();

        // y1 for this step: 8 batches (bs half)
        unsigned long long ya[4] = {0ull, 0ull, 0ull, 0ull};
#pragma unroll
        for (int k = 0; k < U_; k++) {
            const unsigned long long cv = dup2(cy_sh[k * NOUT + o]);
            const ulonglong2 t0 = *(const ulonglong2*)&s_sh[q][k * 16 + bs * 8];
            const ulonglong2 t1 = *(const ulonglong2*)&s_sh[q][k * 16 + bs * 8 + 4];
            ya[0] = ffma2(t0.x, cv, ya[0]);
            ya[1] = ffma2(t0.y, cv, ya[1]);
            ya[2] = ffma2(t1.x, cv, ya[2]);
            ya[3] = ffma2(t1.y, cv, ya[3]);
        }
#pragma unroll
        for (int jj = 0; jj < 4; jj++) {
            float2 f = unpack2(ya[jj]);
            const int bb = b0 + bs * 8 + 2 * jj;
            y[((size_t)bb * T_ + t) * NOUT + o]       = f.x;
            y[((size_t)(bb + 1) * T_ + t) * NOUT + o] = f.y;
        }

        p = q;
#pragma unroll
        for (int j = 0; j < 16; j++) kyc[j] = kyn[j];
    }

#pragma unroll
    for (int j = 0; j < 16; j++)
        g_E[((size_t)(b0 + j) * CCH + c) * U_ + u] = s_sh[p][u * 16 + j];
}

// ---------------------------------------------------------------------------
// K4: carry scan.  carry[b,0]=0; carry[b,c]=carry[b,c-1]@AT^64 + E[b,c-1]
// ---------------------------------------------------------------------------
__global__ __launch_bounds__(128) void pass2_kernel() {
    const int b = blockIdx.x, u = threadIdx.x;
    __shared__ float ss[2][U_];
    float m[U_];
#pragma unroll
    for (int k = 0; k < U_; k++) m[k] = g_P64[k * U_ + u];

    float su = 0.f;
    float e = g_E[((size_t)b * CCH) * U_ + u];
    ss[0][u] = 0.f;
    __syncthreads();

    int p = 0;
#pragma unroll 1
    for (int c = 0; c < CCH; c++) {
        g_carry[((size_t)b * CCH + c) * U_ + u] = su;
        float a0 = e, a1 = 0.f, a2 = 0.f, a3 = 0.f;
        if (c < CCH - 1) e = g_E[((size_t)b * CCH + c + 1) * U_ + u];
#pragma unroll
        for (int k = 0; k < U_; k += 4) {
            a0 = fmaf(ss[p][k + 0], m[k + 0], a0);
            a1 = fmaf(ss[p][k + 1], m[k + 1], a1);
            a2 = fmaf(ss[p][k + 2], m[k + 2], a2);
            a3 = fmaf(ss[p][k + 3], m[k + 3], a3);
        }
        su = (a0 + a1) + (a2 + a3);
        ss[p ^ 1][u] = su;
        __syncthreads();
        p ^= 1;
    }
}

// ---------------------------------------------------------------------------
// K5: W-slab build/doubling. Block j: Wt[:, sout+j, :] = P_j @ Win[j]
// P_j = (j odd) ? Pb : Pa. Win element (m,o) of slab j = Win[m*win_rs + j*jstride + o].
// Output layout g_Wt[k][step][o].
// ---------------------------------------------------------------------------
__global__ __launch_bounds__(512) void wdouble(const float* __restrict__ Pa,
                                               const float* __restrict__ Pb,
                                               const float* __restrict__ Win,
                                               int win_rs, int jstride, int sout) {
    const int j = blockIdx.x;
    const float* P = (j & 1) ? Pb : Pa;
    __shared__ float win_sh[U_ * NOUT];
    const int tid = threadIdx.x;
    for (int idx = tid; idx < U_ * NOUT; idx += 512) {
        int m = idx >> 6, o = idx & 63;
        win_sh[idx] = Win[m * win_rs + j * jstride + o];
    }
    __syncthreads();
    const int o = tid & 63, kg = tid >> 6;  // 8 groups of 16 k
#pragma unroll 1
    for (int ki = 0; ki < 16; ki++) {
        const int k = kg * 16 + ki;
        float a0 = 0.f, a1 = 0.f, a2 = 0.f, a3 = 0.f;
#pragma unroll
        for (int m = 0; m < U_; m += 4) {
            a0 = fmaf(P[k * U_ + m + 0], win_sh[(m + 0) * 64 + o], a0);
            a1 = fmaf(P[k * U_ + m + 1], win_sh[(m + 1) * 64 + o], a1);
            a2 = fmaf(P[k * U_ + m + 2], win_sh[(m + 2) * 64 + o], a2);
            a3 = fmaf(P[k * U_ + m + 3], win_sh[(m + 3) * 64 + o], a3);
        }
        g_Wt[(size_t)k * (LCH * NOUT) + (sout + j) * 64 + o] = (a0 + a1) + (a2 + a3);
    }
}

// ---------------------------------------------------------------------------
// K6: y += carry @ Wt   (GEMM: M=4096 (b,c), N=4096 (step,o), K=128)
// tile 64(M) x 32(N), full K; grid (128 nt, 64 mt); 128 threads.
// ---------------------------------------------------------------------------
__global__ __launch_bounds__(128, 2) void fixup(float* __restrict__ y) {
    const int nt = blockIdx.x, mt = blockIdx.y;
    const int tid = threadIdx.x;
    __shared__ __align__(16) float As[U_ * 64];  // [k][m] 32 KB
    __shared__ __align__(16) float Bs[U_ * 32];  // [k][n] 16 KB

    {   // load carry tile transposed: As[k][m]
        const int mi = tid >> 1, kh = (tid & 1) * 64;
        const float* src = &g_carry[((size_t)(mt * 64 + mi)) * U_ + kh];
#pragma unroll
        for (int i = 0; i < 64; i += 4) {
            float4 v = *(const float4*)(src + i);
            As[(kh + i + 0) * 64 + mi] = v.x;
            As[(kh + i + 1) * 64 + mi] = v.y;
            As[(kh + i + 2) * 64 + mi] = v.z;
            As[(kh + i + 3) * 64 + mi] = v.w;
        }
    }
    {   // load Wt tile: Bs[k][n]
        const float4* src = (const float4*)&g_Wt[(size_t)tid * (LCH * NOUT) + nt * 32];
        float4* dst = (float4*)&Bs[tid * 32];
#pragma unroll
        for (int i = 0; i < 8; i++) dst[i] = src[i];
    }
    __syncthreads();

    const int ni = tid & 7, mi = tid >> 3;
    const int n4 = ni * 4, m4 = mi * 4;

    unsigned long long acc[4][2];
#pragma unroll
    for (int i = 0; i < 4; i++) { acc[i][0] = 0ull; acc[i][1] = 0ull; }

#pragma unroll 8
    for (int k = 0; k < U_; k++) {
        const float4 a = *(const float4*)&As[k * 64 + m4];
        const ulonglong2 b = *(const ulonglong2*)&Bs[k * 32 + n4];
        const unsigned long long a0 = dup2(a.x), a1 = dup2(a.y);
        const unsigned long long a2 = dup2(a.z), a3 = dup2(a.w);
        acc[0][0] = ffma2(b.x, a0, acc[0][0]);
        acc[0][1] = ffma2(b.y, a0, acc[0][1]);
        acc[1][0] = ffma2(b.x, a1, acc[1][0]);
        acc[1][1] = ffma2(b.y, a1, acc[1][1]);
        acc[2][0] = ffma2(b.x, a2, acc[2][0]);
        acc[2][1] = ffma2(b.y, a2, acc[2][1]);
        acc[3][0] = ffma2(b.x, a3, acc[3][0]);
        acc[3][1] = ffma2(b.y, a3, acc[3][1]);
    }

#pragma unroll
    for (int i = 0; i < 4; i++) {
        const int r = mt * 64 + m4 + i;
        float* yp = y + (size_t)r * 4096 + nt * 32 + n4;
        float4 e0 = *(float4*)yp;
        float2 f0 = unpack2(acc[i][0]), f1 = unpack2(acc[i][1]);
        e0.x += f0.x; e0.y += f0.y; e0.z += f1.x; e0.w += f1.y;
        *(float4*)yp = e0;
    }
}

// ---------------------------------------------------------------------------
// Launch. Order chosen so ncu's captured 6th launch is scan1.
// ---------------------------------------------------------------------------
extern "C" void kernel_launch(void* const* d_in, const int* in_sizes, int n_in,
                              void* d_out, int out_size) {
    const float* x   = (const float*)d_in[0];
    const float* AT  = (const float*)d_in[1];
    const float* KT  = (const float*)d_in[2];
    const float* CyT = (const float*)d_in[3];
    float* y = (float*)d_out;

    float *P2, *P4, *P8, *P16, *P32, *P64, *Wt;
    cudaGetSymbolAddress((void**)&P2,  g_P2);
    cudaGetSymbolAddress((void**)&P4,  g_P4);
    cudaGetSymbolAddress((void**)&P8,  g_P8);
    cudaGetSymbolAddress((void**)&P16, g_P16);
    cudaGetSymbolAddress((void**)&P32, g_P32);
    cudaGetSymbolAddress((void**)&P64, g_P64);
    cudaGetSymbolAddress((void**)&Wt,  g_Wt);

    ky_kernel<<<(B_ * T_) / 256, 128>>>(x, KT);          // 1
    matsq<<<128, 128>>>(AT,  P2);                        // 2
    matsq<<<128, 128>>>(P2,  P4);                        // 3
    matsq<<<128, 128>>>(P4,  P8);                        // 4
    matsq<<<128, 128>>>(P8,  P16);                       // 5
    scan1<<<dim3(CCH, B_ / 16), 128>>>(AT, CyT, y);      // 6  <- ncu target
    matsq<<<128, 128>>>(P16, P32);                       // 7
    matsq<<<128, 128>>>(P32, P64);                       // 8
    pass2_kernel<<<B_, 128>>>();                         // 9

    // W build: W[s] = AT^(s+1) @ CyT, layout g_Wt[k][s][o]
    wdouble<<<2, 512>>>(AT,  P2,  CyT, 64,   0,  0);     // W0 = AT@CyT, W1 = AT^2@CyT
    wdouble<<<2, 512>>>(P2,  P2,  Wt,  4096, 64, 2);     // W[2..3]  = P2  @ W[0..1]
    wdouble<<<4, 512>>>(P4,  P4,  Wt,  4096, 64, 4);     // W[4..7]  = P4  @ W[0..3]
    wdouble<<<8, 512>>>(P8,  P8,  Wt,  4096, 64, 8);     // W[8..15]
    wdouble<<<16, 512>>>(P16, P16, Wt, 4096, 64, 16);    // W[16..31]
    wdouble<<<32, 512>>>(P32, P32, Wt, 4096, 64, 32);    // W[32..63]

    fixup<<<dim3(128, 64), 128>>>(y);                    // y += carry @ W
}